// round 9
// baseline (speedup 1.0000x reference)
#include <cuda_runtime.h>
#include <cstdint>
#include <math.h>

#define BATCH 256
#define NCHK  512
#define NVAR  1024
#define DVd   3
#define DD    16
#define EE    3072

#define C_HID  388
#define V_HID  196
#define V_OUT  49

// Persistent message buffers
__device__ float g_Mc[(size_t)BATCH*EE*DD];   // 50.3 MB
__device__ float g_Mv[(size_t)BATCH*EE*DD];   // 50.3 MB

// Fragment-ordered tf32 weight buffers (filled once per launch)
__device__ unsigned g_cW1f[7*7*12*64];        // [cc][nt][kt][lane][2]
__device__ unsigned g_cW2f[7*12*7*64];        // [cc][nt][ktl][lane][2]
__device__ unsigned g_vW1f[4*7*6*64];         // [cc][nt][kt][lane][2]
__device__ unsigned g_vW2f[4*7*7*64];         // [cc][nt][ktl][lane][2]

__device__ __forceinline__ float rcp_fast(float x){
    float r; asm("rcp.approx.f32 %0, %1;" : "=f"(r) : "f"(x)); return r;
}
// Branchless gelu: A&S 7.1.26 erf (max abs err 1.5e-7)
__device__ __forceinline__ float gelu_fast(float x){
    float z = fabsf(x) * 0.7071067811865476f;
    float t = rcp_fast(fmaf(0.3275911f, z, 1.0f));
    float p = fmaf(t, 1.061405429f, -1.453152027f);
    p = fmaf(t, p, 1.421413741f);
    p = fmaf(t, p, -0.284496736f);
    p = fmaf(t, p, 0.254829592f);
    p *= t;
    float e = __expf(-0.5f * x * x);
    float erfa = fmaf(-p, e, 1.0f);
    float s = copysignf(erfa, x);
    return 0.5f * x * (1.0f + s);
}
__device__ __forceinline__ unsigned f2tf32(float x){
    unsigned r; asm("cvt.rn.tf32.f32 %0, %1;" : "=r"(r) : "f"(x)); return r;
}
__device__ __forceinline__ void mma_tf32(float* d, const unsigned* a, unsigned b0, unsigned b1){
    asm volatile("mma.sync.aligned.m16n8k8.row.col.f32.tf32.tf32.f32 "
        "{%0,%1,%2,%3},{%4,%5,%6,%7},{%8,%9},{%0,%1,%2,%3};"
        : "+f"(d[0]),"+f"(d[1]),"+f"(d[2]),"+f"(d[3])
        : "r"(a[0]),"r"(a[1]),"r"(a[2]),"r"(a[3]), "r"(b0),"r"(b1));
}

// 2-warp pair barrier (warps 2m, 2m+1 of a CTA), named barrier id = m+1
#define PAIR_BAR(mg) asm volatile("bar.sync %0, 64;" :: "r"((mg)+1) : "memory")

// ---------------------------------------------------------------------------
__global__ void init_kernel(const float* __restrict__ prior,
                            const int* __restrict__ perm)
{
    int idx = blockIdx.x * blockDim.x + threadIdx.x;
    if (idx >= BATCH*EE*DD) return;
    int d  = idx & (DD-1);
    int bp = idx >> 4;
    int p  = bp % EE;
    int b  = bp / EE;
    int j  = perm[p];
    float v = (d == 0) ? prior[p / DVd] : 0.0f;
    g_Mc[((size_t)b*EE + j)*DD + d] = v;
}

// ---------------------------------------------------------------------------
__global__ void prep_check(const float* __restrict__ W1, const float* __restrict__ W2)
{
    int idx = blockIdx.x*blockDim.x + threadIdx.x;
    if (idx < 37632) {
        int s = idx & 1, l = (idx >> 1) & 31;
        int r = idx >> 6;
        int kt = r % 12; r /= 12;
        int nt = r % 7;  int cc = r / 7;
        int gid = l >> 2, tig = l & 3;
        int k = kt*8 + tig + 4*s;                 // < 96
        int n = cc*56 + nt*8 + gid;
        float v = (n < C_HID) ? W1[k*C_HID + n] : 0.0f;
        g_cW1f[idx] = f2tf32(v);
    } else if (idx < 75264) {
        int j = idx - 37632;
        int s = j & 1, l = (j >> 1) & 31;
        int r = j >> 6;
        int ktl = r % 7; r /= 7;
        int nt = r % 12; int cc = r / 12;
        int gid = l >> 2, tig = l & 3;
        int k = cc*56 + ktl*8 + tig + 4*s;
        int n = nt*8 + gid;                       // < 96
        float v = (k < C_HID) ? W2[k*96 + n] : 0.0f;
        g_cW2f[j] = f2tf32(v);
    }
}

__global__ void prep_var(const float* __restrict__ W1, const float* __restrict__ W2)
{
    int idx = blockIdx.x*blockDim.x + threadIdx.x;
    if (idx < 10752) {
        int s = idx & 1, l = (idx >> 1) & 31;
        int r = idx >> 6;
        int kt = r % 6; r /= 6;
        int nt = r % 7; int cc = r / 7;
        int gid = l >> 2, tig = l & 3;
        int k = kt*8 + tig + 4*s;                 // < 48
        int n = cc*56 + nt*8 + gid;
        float v = (n < V_HID) ? W1[k*V_HID + n] : 0.0f;
        g_vW1f[idx] = f2tf32(v);
    } else if (idx < 23296) {
        int j = idx - 10752;
        int s = j & 1, l = (j >> 1) & 31;
        int r = j >> 6;
        int ktl = r % 7; r /= 7;
        int nt = r % 7; int cc = r / 7;
        int gid = l >> 2, tig = l & 3;
        int k = cc*56 + ktl*8 + tig + 4*s;
        int n = nt*8 + gid;
        float v = (k < V_HID && n < V_OUT) ? W2[k*V_OUT + n] : 0.0f;
        g_vW2f[j] = f2tf32(v);
    }
}

// ---------------------------------------------------------------------------
// CHECK: 131072 rows. 256 thr = 8 warps = 4 pairs. Pair (mg) owns 32 rows;
// warp nh in pair owns half the output columns. B fragments feed 2 m16 MMAs.
// ---------------------------------------------------------------------------
#define UHS 61

__global__ __launch_bounds__(256, 2)
void check_kernel(const int* __restrict__ synd,
                  const float* __restrict__ W1raw, const float* __restrict__ B1,
                  const float* __restrict__ B2)
{
    extern __shared__ unsigned smem[];
    uint4*    sXf  = (uint4*)smem;                 // 4mg*2t*12kt*32 = 3072 uint4
    unsigned* sH   = smem + 12288;                 // 128*61 = 7808 words
    float*    sb1a = (float*)(sH + 128*UHS);       // 392
    float*    sw1r = sb1a + 392;                   // 392
    float*    sb2  = sw1r + 392;                   // 96

    const int tid  = threadIdx.x;
    const int warp = tid >> 5, lane = tid & 31;
    const int mg   = warp >> 1, nh = warp & 1;
    const int gid  = lane >> 2, tig = lane & 3;
    const int base_row = blockIdx.x * 128;
    const int rbase = base_row + mg*32;

    // ---- prologue ----
    for (int i = tid; i < 392; i += 256) {
        bool ok = i < C_HID;
        sb1a[i] = ok ? B1[i] : 0.0f;
        sw1r[i] = ok ? W1raw[96*C_HID + i] : 0.0f;
    }
    if (tid < 96) sb2[tid] = B2[tid];

    // A fragments: warp stages its tile t = nh (rows rbase+nh*16 .. +15)
    {
        const float* xlo = g_Mc + (size_t)(rbase + nh*16 + gid) * 96;
        const float* xhi = g_Mc + (size_t)(rbase + nh*16 + 8 + gid) * 96;
        uint4* dst = sXf + ((mg*2 + nh)*12)*32 + lane;
        #pragma unroll
        for (int kt = 0; kt < 12; kt++) {
            int c = kt*8 + tig;
            uint4 v;
            v.x = f2tf32(xlo[c]);   v.y = f2tf32(xhi[c]);
            v.z = f2tf32(xlo[c+4]); v.w = f2tf32(xhi[c+4]);
            dst[kt*32] = v;
        }
    }
    float sg[4];
    #pragma unroll
    for (int q = 0; q < 4; q++)
        sg[q] = 1.0f - 2.0f * (float)synd[rbase + ((q>>1)<<4) + ((q&1)<<3) + gid];
    __syncthreads();

    const int NT1 = 4 - nh;            // layer1: nh0 -> nt 0..3, nh1 -> nt 4..6
    const int nt0_1 = nh ? 4 : 0;
    const int nt0_2 = nh * 6;          // layer2: 6 tiles each

    float acc2[2][6][4];
    #pragma unroll
    for (int t = 0; t < 2; t++)
        #pragma unroll
        for (int n = 0; n < 6; n++)
            #pragma unroll
            for (int i = 0; i < 4; i++) acc2[t][n][i] = 0.0f;

    const uint4* myX0 = sXf + ((mg*2 + 0)*12)*32 + lane;
    const uint4* myX1 = sXf + ((mg*2 + 1)*12)*32 + lane;

    for (int cc = 0; cc < 7; cc++) {
        // ---- layer 1: m32 x n(32|24), K=96, rank-1 sgn init ----
        float acc1[2][4][4];
        #pragma unroll
        for (int j = 0; j < 4; j++) {
            if (j >= NT1) continue;
            #pragma unroll
            for (int i = 0; i < 4; i++) {
                float w = sw1r[cc*56 + (nt0_1 + j)*8 + 2*tig + (i & 1)];
                acc1[0][j][i] = sg[i >> 1]       * w;
                acc1[1][j][i] = sg[2 + (i >> 1)] * w;
            }
        }
        const uint2* wp1 = (const uint2*)g_cW1f + (size_t)cc*7*12*32 + lane;
        #pragma unroll 4
        for (int kt = 0; kt < 12; kt++) {
            uint4 a04 = myX0[kt*32];
            uint4 a14 = myX1[kt*32];
            unsigned a0[4] = {a04.x, a04.y, a04.z, a04.w};
            unsigned a1[4] = {a14.x, a14.y, a14.z, a14.w};
            #pragma unroll
            for (int j = 0; j < 4; j++) {
                if (j >= NT1) continue;
                uint2 b = __ldg(wp1 + (size_t)((nt0_1 + j)*12 + kt)*32);
                mma_tf32(acc1[0][j], a0, b.x, b.y);
                mma_tf32(acc1[1][j], a1, b.x, b.y);
            }
        }

        // ---- gelu -> H (tf32), warp's columns, pair's 32 rows ----
        #pragma unroll
        for (int j = 0; j < 4; j++) {
            if (j >= NT1) continue;
            #pragma unroll
            for (int t = 0; t < 2; t++) {
                #pragma unroll
                for (int i = 0; i < 4; i++) {
                    int rowloc = mg*32 + t*16 + gid + ((i >> 1) << 3);
                    int colloc = (nt0_1 + j)*8 + 2*tig + (i & 1);
                    float h = gelu_fast(acc1[t][j][i] + sb1a[cc*56 + colloc]);
                    sH[rowloc*UHS + colloc] = f2tf32(h);
                }
            }
        }
        PAIR_BAR(mg);

        // ---- layer 2 partial: m32 x n48, K=56 ----
        const uint2* wp2 = (const uint2*)g_cW2f + (size_t)cc*12*7*32 + lane;
        #pragma unroll 2
        for (int ktl = 0; ktl < 7; ktl++) {
            const unsigned* hb = sH + (mg*32 + gid)*UHS + ktl*8 + tig;
            unsigned a0[4], a1[4];
            a0[0] = hb[0];        a0[1] = hb[8*UHS];
            a0[2] = hb[4];        a0[3] = hb[8*UHS + 4];
            a1[0] = hb[16*UHS];   a1[1] = hb[24*UHS];
            a1[2] = hb[16*UHS+4]; a1[3] = hb[24*UHS + 4];
            #pragma unroll
            for (int j = 0; j < 6; j++) {
                uint2 b = __ldg(wp2 + (size_t)((nt0_2 + j)*7 + ktl)*32);
                mma_tf32(acc2[0][j], a0, b.x, b.y);
                mma_tf32(acc2[1][j], a1, b.x, b.y);
            }
        }
        PAIR_BAR(mg);      // WAR: partner must finish reading H before next write
    }

    // ---- epilogue: Mv = (D + b2) * sgn ----
    #pragma unroll
    for (int j = 0; j < 6; j++) {
        int col = (nt0_2 + j)*8 + 2*tig;
        float bb0 = sb2[col], bb1 = sb2[col+1];
        #pragma unroll
        for (int t = 0; t < 2; t++) {
            #pragma unroll
            for (int half = 0; half < 2; half++) {
                int row = rbase + t*16 + half*8 + gid;
                float sgv = sg[t*2 + half];
                float2 y;
                y.x = (acc2[t][j][half*2+0] + bb0) * sgv;
                y.y = (acc2[t][j][half*2+1] + bb1) * sgv;
                *(float2*)(g_Mv + (size_t)row*96 + col) = y;
            }
        }
    }
}

// ---------------------------------------------------------------------------
// VAR: 262144 rows. Same pair structure: m32/warp, N split 4/3 both layers.
// ---------------------------------------------------------------------------
__global__ __launch_bounds__(256, 2)
void var_kernel(const int* __restrict__ perm,
                const float* __restrict__ prior,
                const float* __restrict__ W1raw, const float* __restrict__ B1,
                const float* __restrict__ B2,
                float* __restrict__ out_llr)
{
    extern __shared__ unsigned smemv[];
    uint4*    sXf  = (uint4*)smemv;                // 4mg*2t*6kt*32 = 1536 uint4
    unsigned* sH   = smemv + 6144;                 // 128*61 words
    float*    sb1a = (float*)(sH + 128*UHS);       // 224
    float*    sw1r = sb1a + 224;                   // 224
    float*    sb2  = sw1r + 224;                   // 49

    const int tid  = threadIdx.x;
    const int warp = tid >> 5, lane = tid & 31;
    const int mg   = warp >> 1, nh = warp & 1;
    const int gid  = lane >> 2, tig = lane & 3;
    const int base_row = blockIdx.x * 128;
    const int rbase = base_row + mg*32;

    for (int i = tid; i < 224; i += 256) {
        bool ok = i < V_HID;
        sb1a[i] = ok ? B1[i] : 0.0f;
        sw1r[i] = ok ? W1raw[48*V_HID + i] : 0.0f;
    }
    if (tid < 49) sb2[tid] = B2[tid];

    int rw[4], bb[4], pp[4][3];
    float pr[4];
    #pragma unroll
    for (int q = 0; q < 4; q++) {
        rw[q] = rbase + ((q>>1)<<4) + ((q&1)<<3) + gid;
        bb[q] = rw[q] >> 10;
        int v = rw[q] & 1023;
        pr[q] = prior[v];
        #pragma unroll
        for (int e = 0; e < 3; e++) pp[q][e] = perm[v*DVd + e];
    }

    // A fragments: warp stages tile t = nh (rows q = 2nh, 2nh+1)
    {
        const float* blo = g_Mv + (size_t)bb[nh*2]  *EE*DD;
        const float* bhi = g_Mv + (size_t)bb[nh*2+1]*EE*DD;
        uint4* dst = sXf + ((mg*2 + nh)*6)*32 + lane;
        #pragma unroll
        for (int kt = 0; kt < 6; kt++) {
            int e = kt >> 1;
            int d = ((kt & 1) << 3) + tig;
            uint4 v;
            v.x = f2tf32(blo[pp[nh*2][e]*DD + d]);
            v.y = f2tf32(bhi[pp[nh*2+1][e]*DD + d]);
            v.z = f2tf32(blo[pp[nh*2][e]*DD + d + 4]);
            v.w = f2tf32(bhi[pp[nh*2+1][e]*DD + d + 4]);
            dst[kt*32] = v;
        }
    }
    __syncthreads();

    const int NT1 = 4 - nh;            // layer1: 4/3 split of 7 tiles
    const int nt0_1 = nh ? 4 : 0;
    const int NT2 = 4 - nh;            // layer2: 4/3 split of 7 tiles
    const int nt0_2 = nh ? 4 : 0;

    float acc2[2][4][4];
    #pragma unroll
    for (int t = 0; t < 2; t++)
        #pragma unroll
        for (int n = 0; n < 4; n++)
            #pragma unroll
            for (int i = 0; i < 4; i++) acc2[t][n][i] = 0.0f;

    const uint4* myX0 = sXf + ((mg*2 + 0)*6)*32 + lane;
    const uint4* myX1 = sXf + ((mg*2 + 1)*6)*32 + lane;

    for (int cc = 0; cc < 4; cc++) {
        float acc1[2][4][4];
        #pragma unroll
        for (int j = 0; j < 4; j++) {
            if (j >= NT1) continue;
            #pragma unroll
            for (int i = 0; i < 4; i++) {
                float w = sw1r[cc*56 + (nt0_1 + j)*8 + 2*tig + (i & 1)];
                acc1[0][j][i] = pr[i >> 1]       * w;
                acc1[1][j][i] = pr[2 + (i >> 1)] * w;
            }
        }
        const uint2* wp1 = (const uint2*)g_vW1f + (size_t)cc*7*6*32 + lane;
        #pragma unroll 3
        for (int kt = 0; kt < 6; kt++) {
            uint4 a04 = myX0[kt*32];
            uint4 a14 = myX1[kt*32];
            unsigned a0[4] = {a04.x, a04.y, a04.z, a04.w};
            unsigned a1[4] = {a14.x, a14.y, a14.z, a14.w};
            #pragma unroll
            for (int j = 0; j < 4; j++) {
                if (j >= NT1) continue;
                uint2 b = __ldg(wp1 + (size_t)((nt0_1 + j)*6 + kt)*32);
                mma_tf32(acc1[0][j], a0, b.x, b.y);
                mma_tf32(acc1[1][j], a1, b.x, b.y);
            }
        }

        #pragma unroll
        for (int j = 0; j < 4; j++) {
            if (j >= NT1) continue;
            #pragma unroll
            for (int t = 0; t < 2; t++) {
                #pragma unroll
                for (int i = 0; i < 4; i++) {
                    int rowloc = mg*32 + t*16 + gid + ((i >> 1) << 3);
                    int colloc = (nt0_1 + j)*8 + 2*tig + (i & 1);
                    float h = gelu_fast(acc1[t][j][i] + sb1a[cc*56 + colloc]);
                    sH[rowloc*UHS + colloc] = f2tf32(h);
                }
            }
        }
        PAIR_BAR(mg);

        const uint2* wp2 = (const uint2*)g_vW2f + (size_t)cc*7*7*32 + lane;
        #pragma unroll 2
        for (int ktl = 0; ktl < 7; ktl++) {
            const unsigned* hb = sH + (mg*32 + gid)*UHS + ktl*8 + tig;
            unsigned a0[4], a1[4];
            a0[0] = hb[0];        a0[1] = hb[8*UHS];
            a0[2] = hb[4];        a0[3] = hb[8*UHS + 4];
            a1[0] = hb[16*UHS];   a1[1] = hb[24*UHS];
            a1[2] = hb[16*UHS+4]; a1[3] = hb[24*UHS + 4];
            #pragma unroll
            for (int j = 0; j < 4; j++) {
                if (j >= NT2) continue;
                uint2 b = __ldg(wp2 + (size_t)((nt0_2 + j)*7 + ktl)*32);
                mma_tf32(acc2[0][j], a0, b.x, b.y);
                mma_tf32(acc2[1][j], a1, b.x, b.y);
            }
        }
        PAIR_BAR(mg);
    }

    // ---- epilogue: scatter via perm regs ----
    #pragma unroll
    for (int j = 0; j < 4; j++) {
        if (j >= NT2) continue;
        #pragma unroll
        for (int t = 0; t < 2; t++) {
            #pragma unroll
            for (int i = 0; i < 4; i++) {
                int col = (nt0_2 + j)*8 + 2*tig + (i & 1);
                if (col > 48) continue;
                int q = t*2 + (i >> 1);
                float y = acc2[t][j][i] + sb2[col];
                if (col < 48) {
                    int e = col >> 4, d = col & 15;
                    g_Mc[((size_t)bb[q]*EE + pp[q][e])*DD + d] = y;
                } else {
                    out_llr[rw[q]] = y;
                }
            }
        }
    }
}

// ---------------------------------------------------------------------------
extern "C" void kernel_launch(void* const* d_in, const int* in_sizes, int n_in,
                              void* d_out, int out_size)
{
    const int*   synd  = (const int*)  d_in[0];
    const float* prior = (const float*)d_in[2];
    const int*   perm  = (const int*)  d_in[3];
    const float* cW1   = (const float*)d_in[4];
    const float* cb1   = (const float*)d_in[5];
    const float* cW2   = (const float*)d_in[6];
    const float* cb2   = (const float*)d_in[7];
    const float* vW1   = (const float*)d_in[8];
    const float* vb1   = (const float*)d_in[9];
    const float* vW2   = (const float*)d_in[10];
    const float* vb2   = (const float*)d_in[11];
    float* out = (float*)d_out;

    const int T = out_size / (BATCH * NVAR);

    const int check_smem = (12288 + 128*UHS)*4 + (392+392+96)*4 + 64;   // ~84 KB
    const int var_smem   = (6144  + 128*UHS)*4 + (224+224+49)*4 + 64;   // ~58 KB

    cudaFuncSetAttribute(check_kernel, cudaFuncAttributeMaxDynamicSharedMemorySize, check_smem);
    cudaFuncSetAttribute(var_kernel,   cudaFuncAttributeMaxDynamicSharedMemorySize, var_smem);

    init_kernel<<<(BATCH*EE*DD + 255)/256, 256>>>(prior, perm);
    prep_check<<<(75264 + 255)/256, 256>>>(cW1, cW2);
    prep_var<<<(23296 + 255)/256, 256>>>(vW1, vW2);

    const int check_blocks = (BATCH*NCHK) / 128;   // 1024
    const int var_blocks   = (BATCH*NVAR) / 128;   // 2048

    for (int t = 0; t < T; t++) {
        check_kernel<<<check_blocks, 256, check_smem>>>(synd, cW1, cb1, cb2);
        var_kernel<<<var_blocks, 256, var_smem>>>(perm, prior, vW1, vb1, vb2,
                                                  out + (size_t)t * BATCH * NVAR);
    }
}

// round 10
// speedup vs baseline: 3.2555x; 3.2555x over previous
#include <cuda_runtime.h>
#include <cuda_fp16.h>
#include <cstdint>
#include <math.h>

#define BATCH 256
#define NCHK  512
#define NVAR  1024
#define DVd   3
#define DD    16
#define EE    3072

#define C_HID  388
#define V_HID  196
#define V_OUT  49

// Persistent message buffers
__device__ float g_Mc[(size_t)BATCH*EE*DD];   // 50.3 MB
__device__ float g_Mv[(size_t)BATCH*EE*DD];   // 50.3 MB

// Fragment-ordered fp16x2 weight buffers (filled once per launch)
// each unsigned = packed f16x2 (elements k, k+1)
__device__ unsigned g_cW1f[7*7*6*64];         // [cc][nt][kt6][lane][s2]  18816
__device__ unsigned g_cW2f[7*12*4*64];        // [cc][nt][ktl4][lane][s2] 21504
__device__ unsigned g_vW1f[4*7*3*64];         // [cc][nt][kt3][lane][s2]   5376
__device__ unsigned g_vW2f[4*7*4*64];         // [cc][nt][ktl4][lane][s2]  7168

__device__ __forceinline__ unsigned packh2(float lo, float hi){
    __half2 h = __floats2half2_rn(lo, hi);
    return *reinterpret_cast<unsigned*>(&h);
}

// Packed tanh-gelu: 0.5x(1+tanh(0.79788456(x + 0.044715 x^3))), f16x2 SIMD
__device__ __forceinline__ unsigned gelu_h2(float lo, float hi){
    __half2 x = __floats2half2_rn(lo, hi);
    const __half2 A  = __floats2half2_rn(0.035677408f, 0.035677408f);  // 0.79788456*0.044715
    const __half2 Bc = __floats2half2_rn(0.79788456f, 0.79788456f);
    const __half2 Hc = __floats2half2_rn(0.5f, 0.5f);
    __half2 u = __hmul2(x, x);
    __half2 v = __hmul2(u, x);
    __half2 tin = __hfma2(v, A, __hmul2(x, Bc));
    unsigned ti = *reinterpret_cast<unsigned*>(&tin);
    unsigned tu;
    asm("tanh.approx.f16x2 %0, %1;" : "=r"(tu) : "r"(ti));
    __half2 t = *reinterpret_cast<__half2*>(&tu);
    __half2 hx = __hmul2(x, Hc);
    __half2 r = __hfma2(hx, t, hx);
    return *reinterpret_cast<unsigned*>(&r);
}

__device__ __forceinline__ void mma_f16(float* d, const unsigned* a, unsigned b0, unsigned b1){
    asm volatile("mma.sync.aligned.m16n8k16.row.col.f32.f16.f16.f32 "
        "{%0,%1,%2,%3},{%4,%5,%6,%7},{%8,%9},{%0,%1,%2,%3};"
        : "+f"(d[0]),"+f"(d[1]),"+f"(d[2]),"+f"(d[3])
        : "r"(a[0]),"r"(a[1]),"r"(a[2]),"r"(a[3]), "r"(b0),"r"(b1));
}

// ---------------------------------------------------------------------------
__global__ void init_kernel(const float* __restrict__ prior,
                            const int* __restrict__ perm)
{
    int idx = blockIdx.x * blockDim.x + threadIdx.x;
    if (idx >= BATCH*EE*DD) return;
    int d  = idx & (DD-1);
    int bp = idx >> 4;
    int p  = bp % EE;
    int b  = bp / EE;
    int j  = perm[p];
    float v = (d == 0) ? prior[p / DVd] : 0.0f;
    g_Mc[((size_t)b*EE + j)*DD + d] = v;
}

// ---------------------------------------------------------------------------
__global__ void prep_check(const float* __restrict__ W1, const float* __restrict__ W2)
{
    int idx = blockIdx.x*blockDim.x + threadIdx.x;
    if (idx < 18816) {
        int l = (idx >> 1) & 31;
        int s = idx & 1;
        int r = idx >> 6;
        int kt = r % 6; r /= 6;
        int nt = r % 7; int cc = r / 7;
        int gid = l >> 2, tig = l & 3;
        int k0 = kt*16 + 2*tig + 8*s;            // 0..94
        int n  = cc*56 + nt*8 + gid;
        float f0 = (n < C_HID) ? W1[k0*C_HID + n] : 0.0f;
        float f1 = (n < C_HID) ? W1[(k0+1)*C_HID + n] : 0.0f;
        g_cW1f[idx] = packh2(f0, f1);
    } else if (idx < 40320) {
        int j = idx - 18816;
        int l = (j >> 1) & 31;
        int s = j & 1;
        int r = j >> 6;
        int ktl = r % 4; r /= 4;
        int nt = r % 12; int cc = r / 12;
        int gid = l >> 2, tig = l & 3;
        int kl   = ktl*16 + 2*tig + 8*s;         // 0..62, even
        int khid = cc*56 + kl;
        int n    = nt*8 + gid;                   // < 96
        bool ok = (kl < 56) && (khid < C_HID);
        float f0 = ok ? W2[khid*96 + n] : 0.0f;
        float f1 = ok ? W2[(khid+1)*96 + n] : 0.0f;
        g_cW2f[j] = packh2(f0, f1);
    }
}

__global__ void prep_var(const float* __restrict__ W1, const float* __restrict__ W2)
{
    int idx = blockIdx.x*blockDim.x + threadIdx.x;
    if (idx < 5376) {
        int l = (idx >> 1) & 31;
        int s = idx & 1;
        int r = idx >> 6;
        int kt = r % 3; r /= 3;
        int nt = r % 7; int cc = r / 7;
        int gid = l >> 2, tig = l & 3;
        int k0 = kt*16 + 2*tig + 8*s;            // 0..46
        int n  = cc*56 + nt*8 + gid;
        float f0 = (n < V_HID) ? W1[k0*V_HID + n] : 0.0f;
        float f1 = (n < V_HID) ? W1[(k0+1)*V_HID + n] : 0.0f;
        g_vW1f[idx] = packh2(f0, f1);
    } else if (idx < 12544) {
        int j = idx - 5376;
        int l = (j >> 1) & 31;
        int s = j & 1;
        int r = j >> 6;
        int ktl = r % 4; r /= 4;
        int nt = r % 7; int cc = r / 7;
        int gid = l >> 2, tig = l & 3;
        int kl   = ktl*16 + 2*tig + 8*s;
        int khid = cc*56 + kl;
        int n    = nt*8 + gid;
        bool ok = (kl < 56) && (khid < V_HID) && (n < V_OUT);
        float f0 = ok ? W2[khid*V_OUT + n] : 0.0f;
        float f1 = ok ? W2[(khid+1)*V_OUT + n] : 0.0f;
        g_vW2f[j] = packh2(f0, f1);
    }
}

// ---------------------------------------------------------------------------
// CHECK: 131072 rows. 256 thr, 8 warps x m16, 128 rows/CTA. fp16 MMA k16.
// sH holds gelu output as f16x2 A-fragment words (stride 36, conflict-free).
// ---------------------------------------------------------------------------
#define SHS 36

__global__ __launch_bounds__(256, 2)
void check_kernel(const int* __restrict__ synd,
                  const float* __restrict__ W1raw, const float* __restrict__ B1,
                  const float* __restrict__ B2)
{
    extern __shared__ unsigned smem[];
    uint4*    sX   = (uint4*)smem;                 // 8w*6kt*32 = 1536 uint4
    unsigned* sH   = smem + 6144;                  // 8*16*36 = 4608 words
    float*    sb1a = (float*)(sH + 8*16*SHS);      // 392
    float*    sw1r = sb1a + 392;                   // 392
    float*    sb2  = sw1r + 392;                   // 96

    const int tid  = threadIdx.x;
    const int warp = tid >> 5, lane = tid & 31;
    const int gid  = lane >> 2, tig = lane & 3;
    const int base_row = blockIdx.x * 128;
    const int r0 = base_row + warp*16 + gid, r1 = r0 + 8;

    // ---- prologue ----
    for (int i = tid; i < 392; i += 256) {
        bool ok = i < C_HID;
        sb1a[i] = ok ? B1[i] : 0.0f;
        sw1r[i] = ok ? W1raw[96*C_HID + i] : 0.0f;
    }
    if (tid < 96) sb2[tid] = B2[tid];

    // stage A fragments (fp16x2)
    {
        const float* x0 = g_Mc + (size_t)r0 * 96;
        const float* x1 = g_Mc + (size_t)r1 * 96;
        uint4* dst = sX + warp*6*32 + lane;
        #pragma unroll
        for (int kt = 0; kt < 6; kt++) {
            int c = kt*16 + 2*tig;
            float2 p00 = *(const float2*)(x0 + c);
            float2 p01 = *(const float2*)(x0 + c + 8);
            float2 p10 = *(const float2*)(x1 + c);
            float2 p11 = *(const float2*)(x1 + c + 8);
            uint4 v;
            v.x = packh2(p00.x, p00.y);
            v.y = packh2(p10.x, p10.y);
            v.z = packh2(p01.x, p01.y);
            v.w = packh2(p11.x, p11.y);
            dst[kt*32] = v;
        }
    }
    const float sg0 = 1.0f - 2.0f * (float)synd[r0];
    const float sg1 = 1.0f - 2.0f * (float)synd[r1];

    // zero pad words (k_local 56..63) in this warp's H region
    unsigned* sHw = sH + warp*16*SHS;
    for (int i = lane; i < 64; i += 32) {
        int rr = i >> 2, w = 28 + (i & 3);
        sHw[rr*SHS + w] = 0;
    }
    __syncthreads();

    float acc2[12][4];
    #pragma unroll
    for (int n = 0; n < 12; n++)
        #pragma unroll
        for (int i = 0; i < 4; i++) acc2[n][i] = 0.0f;

    const uint4* myX = sX + warp*6*32 + lane;

    for (int cc = 0; cc < 7; cc++) {
        // ---- layer 1: m16 x n56, K=96 (6 k16-tiles), rank-1 sgn init ----
        float acc1[7][4];
        #pragma unroll
        for (int nt = 0; nt < 7; nt++) {
            #pragma unroll
            for (int i = 0; i < 4; i++) {
                int gcol = cc*56 + nt*8 + 2*tig + (i & 1);
                acc1[nt][i] = ((i >> 1) ? sg1 : sg0) * sw1r[gcol];
            }
        }
        const uint2* wp1 = (const uint2*)g_cW1f + (size_t)cc*1344 + lane;
        #pragma unroll
        for (int kt = 0; kt < 6; kt++) {
            uint4 a4 = myX[kt*32];
            unsigned a[4] = {a4.x, a4.y, a4.z, a4.w};
            #pragma unroll
            for (int nt = 0; nt < 7; nt++) {
                uint2 b = __ldg(wp1 + (size_t)(nt*6 + kt)*32);
                mma_f16(acc1[nt], a, b.x, b.y);
            }
        }

        // ---- bias + packed gelu -> warp-private H (f16x2 words) ----
        #pragma unroll
        for (int nt = 0; nt < 7; nt++) {
            int c0 = nt*8 + 2*tig;
            float bb0 = sb1a[cc*56 + c0];
            float bb1 = sb1a[cc*56 + c0 + 1];
            unsigned h0 = gelu_h2(acc1[nt][0] + bb0, acc1[nt][1] + bb1);
            unsigned h1 = gelu_h2(acc1[nt][2] + bb0, acc1[nt][3] + bb1);
            sHw[gid*SHS      + nt*4 + tig] = h0;
            sHw[(gid+8)*SHS  + nt*4 + tig] = h1;
        }
        __syncwarp();

        // ---- layer 2 partial: m16 x n96, K=64 (4 k16-tiles, pad zeros) ----
        const uint2* wp2 = (const uint2*)g_cW2f + (size_t)cc*1536 + lane;
        #pragma unroll
        for (int ktl = 0; ktl < 4; ktl++) {
            unsigned a[4];
            a[0] = sHw[gid*SHS     + ktl*8 + tig];
            a[1] = sHw[(gid+8)*SHS + ktl*8 + tig];
            a[2] = sHw[gid*SHS     + ktl*8 + tig + 4];
            a[3] = sHw[(gid+8)*SHS + ktl*8 + tig + 4];
            #pragma unroll
            for (int nt = 0; nt < 12; nt++) {
                uint2 b = __ldg(wp2 + (size_t)(nt*4 + ktl)*32);
                mma_f16(acc2[nt], a, b.x, b.y);
            }
        }
        __syncwarp();
    }

    // ---- epilogue: Mv = (D + b2) * sgn ----
    #pragma unroll
    for (int nt = 0; nt < 12; nt++) {
        int col = nt*8 + 2*tig;
        float bb0 = sb2[col], bb1 = sb2[col+1];
        float2 y0, y1;
        y0.x = (acc2[nt][0] + bb0) * sg0;
        y0.y = (acc2[nt][1] + bb1) * sg0;
        y1.x = (acc2[nt][2] + bb0) * sg1;
        y1.y = (acc2[nt][3] + bb1) * sg1;
        *(float2*)(g_Mv + (size_t)r0*96 + col) = y0;
        *(float2*)(g_Mv + (size_t)r1*96 + col) = y1;
    }
}

// ---------------------------------------------------------------------------
// VAR: 262144 rows. Same structure; gather/scatter via perm. fp16 MMA k16.
// ---------------------------------------------------------------------------
__global__ __launch_bounds__(256, 2)
void var_kernel(const int* __restrict__ perm,
                const float* __restrict__ prior,
                const float* __restrict__ W1raw, const float* __restrict__ B1,
                const float* __restrict__ B2,
                float* __restrict__ out_llr)
{
    extern __shared__ unsigned smemv[];
    uint4*    sX   = (uint4*)smemv;                // 8w*3kt*32 = 768 uint4
    unsigned* sH   = smemv + 3072;                 // 4608 words
    float*    sb1a = (float*)(sH + 8*16*SHS);      // 224
    float*    sw1r = sb1a + 224;                   // 224
    float*    sb2  = sw1r + 224;                   // 49

    const int tid  = threadIdx.x;
    const int warp = tid >> 5, lane = tid & 31;
    const int gid  = lane >> 2, tig = lane & 3;
    const int base_row = blockIdx.x * 128;
    const int r0 = base_row + warp*16 + gid, r1 = r0 + 8;
    const int b0i = r0 >> 10, v0 = r0 & 1023;
    const int b1i = r1 >> 10, v1 = r1 & 1023;

    for (int i = tid; i < 224; i += 256) {
        bool ok = i < V_HID;
        sb1a[i] = ok ? B1[i] : 0.0f;
        sw1r[i] = ok ? W1raw[48*V_HID + i] : 0.0f;
    }
    if (tid < 49) sb2[tid] = B2[tid];

    int p0[3], p1[3];
    #pragma unroll
    for (int e = 0; e < 3; e++) {
        p0[e] = perm[v0*DVd + e];
        p1[e] = perm[v1*DVd + e];
    }
    const float pr0 = prior[v0], pr1 = prior[v1];

    // stage A fragments: kt = e (16 cols per edge)
    {
        const float* base0 = g_Mv + (size_t)b0i*EE*DD;
        const float* base1 = g_Mv + (size_t)b1i*EE*DD;
        uint4* dst = sX + warp*3*32 + lane;
        #pragma unroll
        for (int kt = 0; kt < 3; kt++) {
            const float* q0 = base0 + p0[kt]*DD;
            const float* q1 = base1 + p1[kt]*DD;
            int c = 2*tig;
            float2 p00 = *(const float2*)(q0 + c);
            float2 p01 = *(const float2*)(q0 + c + 8);
            float2 p10 = *(const float2*)(q1 + c);
            float2 p11 = *(const float2*)(q1 + c + 8);
            uint4 v;
            v.x = packh2(p00.x, p00.y);
            v.y = packh2(p10.x, p10.y);
            v.z = packh2(p01.x, p01.y);
            v.w = packh2(p11.x, p11.y);
            dst[kt*32] = v;
        }
    }

    unsigned* sHw = sH + warp*16*SHS;
    for (int i = lane; i < 64; i += 32) {
        int rr = i >> 2, w = 28 + (i & 3);
        sHw[rr*SHS + w] = 0;
    }
    __syncthreads();

    float acc2[7][4];
    #pragma unroll
    for (int n = 0; n < 7; n++)
        #pragma unroll
        for (int i = 0; i < 4; i++) acc2[n][i] = 0.0f;

    const uint4* myX = sX + warp*3*32 + lane;

    for (int cc = 0; cc < 4; cc++) {
        float acc1[7][4];
        #pragma unroll
        for (int nt = 0; nt < 7; nt++) {
            #pragma unroll
            for (int i = 0; i < 4; i++) {
                int gcol = cc*56 + nt*8 + 2*tig + (i & 1);
                acc1[nt][i] = ((i >> 1) ? pr1 : pr0) * sw1r[gcol];
            }
        }
        const uint2* wp1 = (const uint2*)g_vW1f + (size_t)cc*672 + lane;
        #pragma unroll
        for (int kt = 0; kt < 3; kt++) {
            uint4 a4 = myX[kt*32];
            unsigned a[4] = {a4.x, a4.y, a4.z, a4.w};
            #pragma unroll
            for (int nt = 0; nt < 7; nt++) {
                uint2 b = __ldg(wp1 + (size_t)(nt*3 + kt)*32);
                mma_f16(acc1[nt], a, b.x, b.y);
            }
        }

        #pragma unroll
        for (int nt = 0; nt < 7; nt++) {
            int c0 = nt*8 + 2*tig;
            float bb0 = sb1a[cc*56 + c0];
            float bb1 = sb1a[cc*56 + c0 + 1];
            unsigned h0 = gelu_h2(acc1[nt][0] + bb0, acc1[nt][1] + bb1);
            unsigned h1 = gelu_h2(acc1[nt][2] + bb0, acc1[nt][3] + bb1);
            sHw[gid*SHS      + nt*4 + tig] = h0;
            sHw[(gid+8)*SHS  + nt*4 + tig] = h1;
        }
        __syncwarp();

        const uint2* wp2 = (const uint2*)g_vW2f + (size_t)cc*896 + lane;
        #pragma unroll
        for (int ktl = 0; ktl < 4; ktl++) {
            unsigned a[4];
            a[0] = sHw[gid*SHS     + ktl*8 + tig];
            a[1] = sHw[(gid+8)*SHS + ktl*8 + tig];
            a[2] = sHw[gid*SHS     + ktl*8 + tig + 4];
            a[3] = sHw[(gid+8)*SHS + ktl*8 + tig + 4];
            #pragma unroll
            for (int nt = 0; nt < 7; nt++) {
                uint2 b = __ldg(wp2 + (size_t)(nt*4 + ktl)*32);
                mma_f16(acc2[nt], a, b.x, b.y);
            }
        }
        __syncwarp();
    }

    // ---- epilogue: scatter via perm regs ----
    #pragma unroll
    for (int nt = 0; nt < 7; nt++) {
        #pragma unroll
        for (int i = 0; i < 4; i++) {
            int col = nt*8 + 2*tig + (i & 1);
            if (col > 48) continue;
            int rowsel = i >> 1;
            float y = acc2[nt][i] + sb2[col];
            if (col < 48) {
                int e = col >> 4, d = col & 15;
                int p = rowsel ? p1[e] : p0[e];
                int b = rowsel ? b1i : b0i;
                g_Mc[((size_t)b*EE + p)*DD + d] = y;
            } else {
                out_llr[rowsel ? r1 : r0] = y;
            }
        }
    }
}

// ---------------------------------------------------------------------------
extern "C" void kernel_launch(void* const* d_in, const int* in_sizes, int n_in,
                              void* d_out, int out_size)
{
    const int*   synd  = (const int*)  d_in[0];
    const float* prior = (const float*)d_in[2];
    const int*   perm  = (const int*)  d_in[3];
    const float* cW1   = (const float*)d_in[4];
    const float* cb1   = (const float*)d_in[5];
    const float* cW2   = (const float*)d_in[6];
    const float* cb2   = (const float*)d_in[7];
    const float* vW1   = (const float*)d_in[8];
    const float* vb1   = (const float*)d_in[9];
    const float* vW2   = (const float*)d_in[10];
    const float* vb2   = (const float*)d_in[11];
    float* out = (float*)d_out;

    const int T = out_size / (BATCH * NVAR);

    const int check_smem = (6144 + 4608)*4 + (392+392+96)*4 + 64;   // ~46.6 KB
    const int var_smem   = (3072 + 4608)*4 + (224+224+49)*4 + 64;   // ~32.8 KB

    cudaFuncSetAttribute(check_kernel, cudaFuncAttributeMaxDynamicSharedMemorySize, check_smem);
    cudaFuncSetAttribute(var_kernel,   cudaFuncAttributeMaxDynamicSharedMemorySize, var_smem);

    init_kernel<<<(BATCH*EE*DD + 255)/256, 256>>>(prior, perm);
    prep_check<<<(40320 + 255)/256, 256>>>(cW1, cW2);
    prep_var<<<(12544 + 255)/256, 256>>>(vW1, vW2);

    const int check_blocks = (BATCH*NCHK) / 128;   // 1024
    const int var_blocks   = (BATCH*NVAR) / 128;   // 2048

    for (int t = 0; t < T; t++) {
        check_kernel<<<check_blocks, 256, check_smem>>>(synd, cW1, cb1, cb2);
        var_kernel<<<var_blocks, 256, var_smem>>>(perm, prior, vW1, vb1, vb2,
                                                  out + (size_t)t * BATCH * NVAR);
    }
}